// round 5
// baseline (speedup 1.0000x reference)
#include <cuda_runtime.h>
#include <cuda_bf16.h>
#include <cstdint>

#define B_    4
#define CIN_  256
#define P_    4096
#define K_    9
#define RDIM  2304          // CIN*9
#define COUT_ 256
#define NTOT  16384         // B*P

// ---------------------------------------------------------------------------
// Device scratch (static — no cudaMalloc allowed)
// ---------------------------------------------------------------------------
__device__ __align__(128) __nv_bfloat16 g_hi[(size_t)RDIM * NTOT];
__device__ __align__(128) __nv_bfloat16 g_lo[(size_t)RDIM * NTOT];
__device__ __align__(128) __nv_bfloat16 g_whi[COUT_ * RDIM];
__device__ __align__(128) __nv_bfloat16 g_wlo[COUT_ * RDIM];

__device__ __forceinline__ uint32_t smem_u32(const void* p) {
    uint32_t a;
    asm("{ .reg .u64 t; cvta.to.shared.u64 t, %1; cvt.u32.u64 %0, t; }"
        : "=r"(a) : "l"(p));
    return a;
}

#define CP16(dst, src) \
    asm volatile("cp.async.cg.shared.global [%0], [%1], 16;" \
                 :: "r"(dst), "l"(src) : "memory")
#define CP_COMMIT() asm volatile("cp.async.commit_group;" ::: "memory")
#define CP_WAIT1()  asm volatile("cp.async.wait_group 1;" ::: "memory")

#define LDMX4(r0, r1, r2, r3, a) \
    asm volatile("ldmatrix.sync.aligned.m8n8.x4.shared.b16 {%0,%1,%2,%3}, [%4];" \
                 : "=r"(r0), "=r"(r1), "=r"(r2), "=r"(r3) : "r"(a))
#define LDMX4T(r0, r1, r2, r3, a) \
    asm volatile("ldmatrix.sync.aligned.m8n8.x4.trans.shared.b16 {%0,%1,%2,%3}, [%4];" \
                 : "=r"(r0), "=r"(r1), "=r"(r2), "=r"(r3) : "r"(a))

#define MMA16816(d, a, b0, b1) \
    asm volatile("mma.sync.aligned.m16n8k16.row.col.f32.bf16.bf16.f32 " \
                 "{%0,%1,%2,%3},{%4,%5,%6,%7},{%8,%9},{%0,%1,%2,%3};" \
                 : "+f"((d)[0]), "+f"((d)[1]), "+f"((d)[2]), "+f"((d)[3]) \
                 : "r"((a)[0]), "r"((a)[1]), "r"((a)[2]), "r"((a)[3]), \
                   "r"(b0), "r"(b1))

// ---------------------------------------------------------------------------
// Kernel 1: weight split (folded in) + fused sampling + im2col -> bf16 hi/lo
// ---------------------------------------------------------------------------
__global__ void im2col_kernel(const float* __restrict__ x,
                              const float* __restrict__ offset,
                              const float* __restrict__ mask,
                              const float* __restrict__ weight) {
    int p = blockIdx.x * blockDim.x + threadIdx.x;
    int k = blockIdx.y;
    int b = blockIdx.z;

    // ---- folded weight split: 589824 = 4 * 147456 total threads
    {
        int t = ((b * 9 + k) << 12) + p;   // 0..147455
        #pragma unroll
        for (int j = 0; j < 4; j++) {
            int i = t + j * 147456;
            float v = weight[i];
            __nv_bfloat16 h = __float2bfloat16(v);
            g_whi[i] = h;
            g_wlo[i] = __float2bfloat16(v - __bfloat162float(h));
        }
    }

    int oy = p >> 6, ox = p & 63;
    int kh = k / 3, kw = k - kh * 3;

    const float* offb = offset + (b * 18 + 2 * k) * P_;
    float dy = offb[p];
    float dx = offb[P_ + p];
    float m  = mask[(b * 9 + k) * P_ + p];

    float sy = (float)(oy - 1 + kh) + dy;
    float sx = (float)(ox - 1 + kw) + dx;
    float y0f = floorf(sy), x0f = floorf(sx);
    float wy = sy - y0f,    wx = sx - x0f;
    int y0 = (int)y0f, x0 = (int)x0f;
    int y1 = y0 + 1,   x1 = x0 + 1;

    bool vy0 = ((unsigned)y0 < 64u), vy1 = ((unsigned)y1 < 64u);
    bool vx0 = ((unsigned)x0 < 64u), vx1 = ((unsigned)x1 < 64u);
    int cy0 = min(max(y0, 0), 63), cy1 = min(max(y1, 0), 63);
    int cx0 = min(max(x0, 0), 63), cx1 = min(max(x1, 0), 63);
    int i00 = cy0 * 64 + cx0, i01 = cy0 * 64 + cx1;
    int i10 = cy1 * 64 + cx0, i11 = cy1 * 64 + cx1;

    float w00 = (1.f - wy) * (1.f - wx) * m; if (!(vy0 && vx0)) w00 = 0.f;
    float w01 = (1.f - wy) * wx * m;         if (!(vy0 && vx1)) w01 = 0.f;
    float w10 = wy * (1.f - wx) * m;         if (!(vy1 && vx0)) w10 = 0.f;
    float w11 = wy * wx * m;                 if (!(vy1 && vx1)) w11 = 0.f;

    const float* xb = x + b * (CIN_ * P_);
    size_t n = (size_t)b * P_ + p;

    #pragma unroll 4
    for (int c = 0; c < CIN_; c++) {
        const float* xp = xb + c * P_;
        float v = w00 * __ldg(xp + i00) + w01 * __ldg(xp + i01)
                + w10 * __ldg(xp + i10) + w11 * __ldg(xp + i11);
        __nv_bfloat16 h = __float2bfloat16(v);
        __nv_bfloat16 l = __float2bfloat16(v - __bfloat162float(h));
        size_t idx = (size_t)(c * 9 + k) * NTOT + n;
        g_hi[idx] = h;
        g_lo[idx] = l;
    }
}

// ---------------------------------------------------------------------------
// Kernel 2: bf16 split-precision GEMM via mma.sync (HMMA)
//   C[256 x 16384] = W[256 x 2304] * cols[2304 x 16384] + bias
//   CTA 128x128, K-chunk 64, 8 warps (2x4), warp tile 64x32, 3-stage cp.async.
// ---------------------------------------------------------------------------
#define BK      64
#define NCH     (RDIM / BK)       // 36
#define A_STRIDE 144              // bytes per m-row (128 data + 16 pad)
#define B_STRIDE 272              // bytes per k-row (256 data + 16 pad)
#define OFF_AH  0
#define OFF_AL  (128 * A_STRIDE)              // 18432
#define OFF_BH  (2 * 128 * A_STRIDE)          // 36864
#define OFF_BL  (OFF_BH + 64 * B_STRIDE)      // 54272
#define STAGE_BYTES (OFF_BL + 64 * B_STRIDE)  // 71680
#define SMEM_TOTAL (3 * STAGE_BYTES)          // 215040

__global__ __launch_bounds__(256, 1) void gemm_mma_kernel(
    const float* __restrict__ bias, float* __restrict__ out)
{
    extern __shared__ char smem[];
    const uint32_t sb0 = smem_u32(smem);
    const int tid = threadIdx.x;
    const int lane = tid & 31, wid = tid >> 5;
    const int warp_m = wid >> 2;          // 0..1  -> m offset *64
    const int warp_n = wid & 3;           // 0..3  -> n offset *32
    const int bm = blockIdx.y * 128;
    const int n0 = blockIdx.x * 128;

    // ldmatrix lane-address components
    const int lgrp = lane >> 3, lr = lane & 7;
    const int a_row   = ((lgrp & 1) << 3) + lr;   // 0..15
    const int a_chunk = lgrp >> 1;                // 0..1 (16B chunk of k16)
    const int b_krow  = ((lgrp & 1) << 3) + lr;   // 0..15
    const int b_col   = (warp_n << 5) + ((lgrp >> 1) << 3);

    const __nv_bfloat16* WH = g_whi + (size_t)bm * RDIM;
    const __nv_bfloat16* WL = g_wlo + (size_t)bm * RDIM;

    // cp.async indexing
    const int a_r = tid >> 1, a_h = tid & 1;   // A: 128 rows, 8x16B per row
    const int b_r = tid >> 4, b_c = tid & 15;  // B: 64 rows, 16x16B per row

    float d[4][4][4];
    #pragma unroll
    for (int i = 0; i < 4; i++)
        #pragma unroll
        for (int j = 0; j < 4; j++)
            #pragma unroll
            for (int q = 0; q < 4; q++) d[i][j][q] = 0.f;

    auto load_stage = [&](int ch) {
        const int kc0 = ch * BK;
        const uint32_t st = sb0 + (ch % 3) * STAGE_BYTES;
        #pragma unroll
        for (int q = 0; q < 4; q++) {
            int c16 = a_h + q * 2;                       // 0..7
            uint32_t dsta = st + OFF_AH + a_r * A_STRIDE + c16 * 16;
            size_t go = (size_t)a_r * RDIM + kc0 + c16 * 8;
            CP16(dsta, WH + go);
            CP16(dsta + (OFF_AL - OFF_AH), WL + go);
        }
        #pragma unroll
        for (int q = 0; q < 4; q++) {
            int r = b_r + q * 16;                        // 0..63
            uint32_t dstb = st + OFF_BH + r * B_STRIDE + b_c * 16;
            size_t go = (size_t)(kc0 + r) * NTOT + n0 + b_c * 8;
            CP16(dstb, g_hi + go);
            CP16(dstb + (OFF_BL - OFF_BH), g_lo + go);
        }
    };

    load_stage(0); CP_COMMIT();
    load_stage(1); CP_COMMIT();

    for (int ch = 0; ch < NCH; ch++) {
        CP_WAIT1();
        __syncthreads();
        if (ch + 2 < NCH) load_stage(ch + 2);
        CP_COMMIT();

        const uint32_t st = sb0 + (ch % 3) * STAGE_BYTES;
        const uint32_t aHbase = st + OFF_AH +
            (warp_m * 64 + a_row) * A_STRIDE + a_chunk * 16;
        const uint32_t bHbase = st + OFF_BH + b_krow * B_STRIDE + b_col * 2;

        #pragma unroll
        for (int s = 0; s < 4; s++) {      // four k16 steps
            uint32_t afh[4][4], afl[4][4], bfh[2][4], bfl[2][4];
            #pragma unroll
            for (int i = 0; i < 4; i++) {
                uint32_t aa = aHbase + i * (16 * A_STRIDE) + s * 32;
                LDMX4(afh[i][0], afh[i][1], afh[i][2], afh[i][3], aa);
                LDMX4(afl[i][0], afl[i][1], afl[i][2], afl[i][3],
                      aa + (OFF_AL - OFF_AH));
            }
            #pragma unroll
            for (int g = 0; g < 2; g++) {
                uint32_t ba = bHbase + s * (16 * B_STRIDE) + g * 32;
                LDMX4T(bfh[g][0], bfh[g][1], bfh[g][2], bfh[g][3], ba);
                LDMX4T(bfl[g][0], bfl[g][1], bfl[g][2], bfl[g][3],
                       ba + (OFF_BL - OFF_BH));
            }
            // Product-major passes: no back-to-back RAW on any accumulator.
            #pragma unroll
            for (int i = 0; i < 4; i++)
                #pragma unroll
                for (int g = 0; g < 2; g++)
                    #pragma unroll
                    for (int jn = 0; jn < 2; jn++)
                        MMA16816(d[i][g * 2 + jn], afh[i],
                                 bfh[g][jn * 2], bfh[g][jn * 2 + 1]);
            #pragma unroll
            for (int i = 0; i < 4; i++)
                #pragma unroll
                for (int g = 0; g < 2; g++)
                    #pragma unroll
                    for (int jn = 0; jn < 2; jn++)
                        MMA16816(d[i][g * 2 + jn], afh[i],
                                 bfl[g][jn * 2], bfl[g][jn * 2 + 1]);
            #pragma unroll
            for (int i = 0; i < 4; i++)
                #pragma unroll
                for (int g = 0; g < 2; g++)
                    #pragma unroll
                    for (int jn = 0; jn < 2; jn++)
                        MMA16816(d[i][g * 2 + jn], afl[i],
                                 bfh[g][jn * 2], bfh[g][jn * 2 + 1]);
        }
    }

    // ---- epilogue ----
    const int row0 = lane >> 2, col0 = (lane & 3) * 2;
    const int bb = n0 >> 12;
    const int pbase = (n0 & 4095) + warp_n * 32 + col0;
    #pragma unroll
    for (int i = 0; i < 4; i++) {
        int co = bm + warp_m * 64 + i * 16 + row0;
        float bi0 = __ldg(bias + co);
        float bi1 = __ldg(bias + co + 8);
        float* o0 = out + ((size_t)(bb * COUT_ + co)) * P_ + pbase;
        float* o1 = o0 + 8 * P_;
        #pragma unroll
        for (int j = 0; j < 4; j++) {
            float2 v0 = make_float2(d[i][j][0] + bi0, d[i][j][1] + bi0);
            float2 v1 = make_float2(d[i][j][2] + bi1, d[i][j][3] + bi1);
            *(float2*)(o0 + j * 8) = v0;
            *(float2*)(o1 + j * 8) = v1;
        }
    }
}

// ---------------------------------------------------------------------------
extern "C" void kernel_launch(void* const* d_in, const int* in_sizes, int n_in,
                              void* d_out, int out_size) {
    const float* x      = (const float*)d_in[0];
    const float* offset = (const float*)d_in[1];
    const float* mask   = (const float*)d_in[2];
    const float* weight = (const float*)d_in[3];
    const float* bias   = (const float*)d_in[4];
    float* out = (float*)d_out;

    cudaFuncSetAttribute(gemm_mma_kernel,
                         cudaFuncAttributeMaxDynamicSharedMemorySize, SMEM_TOTAL);

    im2col_kernel<<<dim3(P_ / 128, K_, B_), 128>>>(x, offset, mask, weight);
    gemm_mma_kernel<<<dim3(NTOT / 128, COUT_ / 128), 256, SMEM_TOTAL>>>(bias, out);
}

// round 6
// speedup vs baseline: 1.0756x; 1.0756x over previous
#include <cuda_runtime.h>
#include <cuda_bf16.h>
#include <cstdint>

#define B_    4
#define CIN_  256
#define P_    4096
#define K_    9
#define RDIM  2304          // CIN*9
#define COUT_ 256
#define NTOT  16384         // B*P

// ---------------------------------------------------------------------------
// Device scratch (static — no cudaMalloc allowed)
// ---------------------------------------------------------------------------
__device__ __align__(128) __nv_bfloat16 g_hi[(size_t)RDIM * NTOT];
__device__ __align__(128) __nv_bfloat16 g_lo[(size_t)RDIM * NTOT];
__device__ __align__(128) __nv_bfloat16 g_whi[COUT_ * RDIM];
__device__ __align__(128) __nv_bfloat16 g_wlo[COUT_ * RDIM];

__device__ __forceinline__ uint32_t smem_u32(const void* p) {
    uint32_t a;
    asm("{ .reg .u64 t; cvta.to.shared.u64 t, %1; cvt.u32.u64 %0, t; }"
        : "=r"(a) : "l"(p));
    return a;
}

#define CP16(dst, src) \
    asm volatile("cp.async.cg.shared.global [%0], [%1], 16;" \
                 :: "r"(dst), "l"(src) : "memory")
#define CP_COMMIT() asm volatile("cp.async.commit_group;" ::: "memory")
#define CP_WAIT1()  asm volatile("cp.async.wait_group 1;" ::: "memory")

#define LDMX4(r0, r1, r2, r3, a) \
    asm volatile("ldmatrix.sync.aligned.m8n8.x4.shared.b16 {%0,%1,%2,%3}, [%4];" \
                 : "=r"(r0), "=r"(r1), "=r"(r2), "=r"(r3) : "r"(a))
#define LDMX4T(r0, r1, r2, r3, a) \
    asm volatile("ldmatrix.sync.aligned.m8n8.x4.trans.shared.b16 {%0,%1,%2,%3}, [%4];" \
                 : "=r"(r0), "=r"(r1), "=r"(r2), "=r"(r3) : "r"(a))

#define MMA16816(d, a, b0, b1) \
    asm volatile("mma.sync.aligned.m16n8k16.row.col.f32.bf16.bf16.f32 " \
                 "{%0,%1,%2,%3},{%4,%5,%6,%7},{%8,%9},{%0,%1,%2,%3};" \
                 : "+f"((d)[0]), "+f"((d)[1]), "+f"((d)[2]), "+f"((d)[3]) \
                 : "r"((a)[0]), "r"((a)[1]), "r"((a)[2]), "r"((a)[3]), \
                   "r"(b0), "r"(b1))

// ---------------------------------------------------------------------------
// Kernel 1: weight split (folded) + fused sampling + im2col -> bf16 hi/lo
// ---------------------------------------------------------------------------
__global__ void im2col_kernel(const float* __restrict__ x,
                              const float* __restrict__ offset,
                              const float* __restrict__ mask,
                              const float* __restrict__ weight) {
    int p = blockIdx.x * blockDim.x + threadIdx.x;
    int k = blockIdx.y;
    int b = blockIdx.z;

    // ---- folded weight split: 589824 = 4 * 147456 total threads
    {
        int t = ((b * 9 + k) << 12) + p;
        #pragma unroll
        for (int j = 0; j < 4; j++) {
            int i = t + j * 147456;
            float v = weight[i];
            __nv_bfloat16 h = __float2bfloat16(v);
            g_whi[i] = h;
            g_wlo[i] = __float2bfloat16(v - __bfloat162float(h));
        }
    }

    int oy = p >> 6, ox = p & 63;
    int kh = k / 3, kw = k - kh * 3;

    const float* offb = offset + (b * 18 + 2 * k) * P_;
    float dy = offb[p];
    float dx = offb[P_ + p];
    float m  = mask[(b * 9 + k) * P_ + p];

    float sy = (float)(oy - 1 + kh) + dy;
    float sx = (float)(ox - 1 + kw) + dx;
    float y0f = floorf(sy), x0f = floorf(sx);
    float wy = sy - y0f,    wx = sx - x0f;
    int y0 = (int)y0f, x0 = (int)x0f;
    int y1 = y0 + 1,   x1 = x0 + 1;

    bool vy0 = ((unsigned)y0 < 64u), vy1 = ((unsigned)y1 < 64u);
    bool vx0 = ((unsigned)x0 < 64u), vx1 = ((unsigned)x1 < 64u);
    int cy0 = min(max(y0, 0), 63), cy1 = min(max(y1, 0), 63);
    int cx0 = min(max(x0, 0), 63), cx1 = min(max(x1, 0), 63);
    int i00 = cy0 * 64 + cx0, i01 = cy0 * 64 + cx1;
    int i10 = cy1 * 64 + cx0, i11 = cy1 * 64 + cx1;

    float w00 = (1.f - wy) * (1.f - wx) * m; if (!(vy0 && vx0)) w00 = 0.f;
    float w01 = (1.f - wy) * wx * m;         if (!(vy0 && vx1)) w01 = 0.f;
    float w10 = wy * (1.f - wx) * m;         if (!(vy1 && vx0)) w10 = 0.f;
    float w11 = wy * wx * m;                 if (!(vy1 && vx1)) w11 = 0.f;

    const float* xb = x + b * (CIN_ * P_);
    size_t n = (size_t)b * P_ + p;

    #pragma unroll 4
    for (int c = 0; c < CIN_; c++) {
        const float* xp = xb + c * P_;
        float v = w00 * __ldg(xp + i00) + w01 * __ldg(xp + i01)
                + w10 * __ldg(xp + i10) + w11 * __ldg(xp + i11);
        __nv_bfloat16 h = __float2bfloat16(v);
        __nv_bfloat16 l = __float2bfloat16(v - __bfloat162float(h));
        size_t idx = (size_t)(c * 9 + k) * NTOT + n;
        g_hi[idx] = h;
        g_lo[idx] = l;
    }
}

// ---------------------------------------------------------------------------
// Kernel 2: bf16 split-precision GEMM via mma.sync (HMMA)
//   CTA 128x128, K-chunk 64, 16 warps (4x4), warp tile 32x32, 3-stage cp.async
// ---------------------------------------------------------------------------
#define BK      64
#define NCH     (RDIM / BK)       // 36
#define A_STRIDE 144              // bytes per m-row (128 data + 16 pad)
#define B_STRIDE 272              // bytes per k-row (256 data + 16 pad)
#define OFF_AH  0
#define OFF_AL  (128 * A_STRIDE)              // 18432
#define OFF_BH  (2 * 128 * A_STRIDE)          // 36864
#define OFF_BL  (OFF_BH + 64 * B_STRIDE)      // 54272
#define STAGE_BYTES (OFF_BL + 64 * B_STRIDE)  // 71680
#define SMEM_TOTAL (3 * STAGE_BYTES)          // 215040

__global__ __launch_bounds__(512, 1) void gemm_mma_kernel(
    const float* __restrict__ bias, float* __restrict__ out)
{
    extern __shared__ char smem[];
    const uint32_t sb0 = smem_u32(smem);
    const int tid = threadIdx.x;
    const int lane = tid & 31, wid = tid >> 5;
    const int warp_m = wid >> 2;          // 0..3  -> m offset *32
    const int warp_n = wid & 3;           // 0..3  -> n offset *32
    const int bm = blockIdx.y * 128;
    const int n0 = blockIdx.x * 128;

    // ldmatrix lane-address components
    const int lgrp = lane >> 3, lr = lane & 7;
    const int a_row   = ((lgrp & 1) << 3) + lr;   // 0..15
    const int a_chunk = lgrp >> 1;                // 0..1 (16B chunk of k16)
    const int b_krow  = ((lgrp & 1) << 3) + lr;   // 0..15
    const int b_col   = (warp_n << 5) + ((lgrp >> 1) << 3);

    const __nv_bfloat16* WH = g_whi + (size_t)bm * RDIM;
    const __nv_bfloat16* WL = g_wlo + (size_t)bm * RDIM;

    // cp.async indexing (512 threads, 8 CP16 each per stage)
    const int a_r = tid >> 2, a_h = tid & 3;   // A: 128 rows, 8x16B per row
    const int b_r = tid >> 3, b_c = tid & 7;   // B: 64 rows, 16x16B per row

    float d[2][4][4];
    #pragma unroll
    for (int i = 0; i < 2; i++)
        #pragma unroll
        for (int j = 0; j < 4; j++)
            #pragma unroll
            for (int q = 0; q < 4; q++) d[i][j][q] = 0.f;

    auto load_stage = [&](int ch) {
        const int kc0 = ch * BK;
        const uint32_t st = sb0 + (ch % 3) * STAGE_BYTES;
        #pragma unroll
        for (int q = 0; q < 2; q++) {
            int c16 = a_h + q * 4;                       // 0..7
            uint32_t dsta = st + OFF_AH + a_r * A_STRIDE + c16 * 16;
            size_t go = (size_t)a_r * RDIM + kc0 + c16 * 8;
            CP16(dsta, WH + go);
            CP16(dsta + (OFF_AL - OFF_AH), WL + go);
        }
        #pragma unroll
        for (int q = 0; q < 2; q++) {
            int c16 = b_c + q * 8;                       // 0..15
            uint32_t dstb = st + OFF_BH + b_r * B_STRIDE + c16 * 16;
            size_t go = (size_t)(kc0 + b_r) * NTOT + n0 + c16 * 8;
            CP16(dstb, g_hi + go);
            CP16(dstb + (OFF_BL - OFF_BH), g_lo + go);
        }
    };

    load_stage(0); CP_COMMIT();
    load_stage(1); CP_COMMIT();

    for (int ch = 0; ch < NCH; ch++) {
        CP_WAIT1();
        __syncthreads();
        if (ch + 2 < NCH) load_stage(ch + 2);
        CP_COMMIT();

        const uint32_t st = sb0 + (ch % 3) * STAGE_BYTES;
        const uint32_t aHbase = st + OFF_AH +
            (warp_m * 32 + a_row) * A_STRIDE + a_chunk * 16;
        const uint32_t bHbase = st + OFF_BH + b_krow * B_STRIDE + b_col * 2;

        #pragma unroll
        for (int s = 0; s < 4; s++) {      // four k16 steps
            uint32_t afh[2][4], afl[2][4], bfh[2][4], bfl[2][4];
            #pragma unroll
            for (int i = 0; i < 2; i++) {
                uint32_t aa = aHbase + i * (16 * A_STRIDE) + s * 32;
                LDMX4(afh[i][0], afh[i][1], afh[i][2], afh[i][3], aa);
                LDMX4(afl[i][0], afl[i][1], afl[i][2], afl[i][3],
                      aa + (OFF_AL - OFF_AH));
            }
            #pragma unroll
            for (int g = 0; g < 2; g++) {
                uint32_t ba = bHbase + s * (16 * B_STRIDE) + g * 32;
                LDMX4T(bfh[g][0], bfh[g][1], bfh[g][2], bfh[g][3], ba);
                LDMX4T(bfl[g][0], bfl[g][1], bfl[g][2], bfl[g][3],
                       ba + (OFF_BL - OFF_BH));
            }
            // Product-major passes: no back-to-back RAW on any accumulator.
            #pragma unroll
            for (int i = 0; i < 2; i++)
                #pragma unroll
                for (int g = 0; g < 2; g++)
                    #pragma unroll
                    for (int jn = 0; jn < 2; jn++)
                        MMA16816(d[i][g * 2 + jn], afh[i],
                                 bfh[g][jn * 2], bfh[g][jn * 2 + 1]);
            #pragma unroll
            for (int i = 0; i < 2; i++)
                #pragma unroll
                for (int g = 0; g < 2; g++)
                    #pragma unroll
                    for (int jn = 0; jn < 2; jn++)
                        MMA16816(d[i][g * 2 + jn], afh[i],
                                 bfl[g][jn * 2], bfl[g][jn * 2 + 1]);
            #pragma unroll
            for (int i = 0; i < 2; i++)
                #pragma unroll
                for (int g = 0; g < 2; g++)
                    #pragma unroll
                    for (int jn = 0; jn < 2; jn++)
                        MMA16816(d[i][g * 2 + jn], afl[i],
                                 bfh[g][jn * 2], bfh[g][jn * 2 + 1]);
        }
    }

    // ---- epilogue ----
    const int row0 = lane >> 2, col0 = (lane & 3) * 2;
    const int bb = n0 >> 12;
    const int pbase = (n0 & 4095) + warp_n * 32 + col0;
    #pragma unroll
    for (int i = 0; i < 2; i++) {
        int co = bm + warp_m * 32 + i * 16 + row0;
        float bi0 = __ldg(bias + co);
        float bi1 = __ldg(bias + co + 8);
        float* o0 = out + ((size_t)(bb * COUT_ + co)) * P_ + pbase;
        float* o1 = o0 + 8 * P_;
        #pragma unroll
        for (int j = 0; j < 4; j++) {
            float2 v0 = make_float2(d[i][j][0] + bi0, d[i][j][1] + bi0);
            float2 v1 = make_float2(d[i][j][2] + bi1, d[i][j][3] + bi1);
            *(float2*)(o0 + j * 8) = v0;
            *(float2*)(o1 + j * 8) = v1;
        }
    }
}

// ---------------------------------------------------------------------------
extern "C" void kernel_launch(void* const* d_in, const int* in_sizes, int n_in,
                              void* d_out, int out_size) {
    const float* x      = (const float*)d_in[0];
    const float* offset = (const float*)d_in[1];
    const float* mask   = (const float*)d_in[2];
    const float* weight = (const float*)d_in[3];
    const float* bias   = (const float*)d_in[4];
    float* out = (float*)d_out;

    cudaFuncSetAttribute(gemm_mma_kernel,
                         cudaFuncAttributeMaxDynamicSharedMemorySize, SMEM_TOTAL);

    im2col_kernel<<<dim3(P_ / 128, K_, B_), 128>>>(x, offset, mask, weight);
    gemm_mma_kernel<<<dim3(NTOT / 128, COUT_ / 128), 512, SMEM_TOTAL>>>(bias, out);
}